// round 16
// baseline (speedup 1.0000x reference)
#include <cuda_runtime.h>
#include <cuda_bf16.h>
#include <cstdint>

// DotInteract: out[b] = concat(dense[b] (128), triu(C C^T) (378)),
// C = [dense[b]; sparse[b,0..25]] (27x128 fp32). B = 32768, OUTW = 506.
//
// One warp per sample; Gram via mma.sync.m16n8k16 bf16, hi+lo split, 3 passes
// (err ~3e-6). Fragments built directly from a cp.async'd raw fp32 buffer via
// LDS.64 + in-register split; A-frag regs double as B-frags (C.C^T symmetry).
// R16 (= R15 resubmit after infra failure): 8 CTAs/SM push. 32-float chunk
// buffer, 27 rows (RAWSTR 160 -> 17280 B/CTA), frag rows >26 clamped to 26
// (garbage only reaches discarded Gram entries >=27), __launch_bounds__(128,8)
// -> 64 regs. Only one k-step's fragments live at a time.

#define THREADS 128
#define WPC     4                    // warps = samples per CTA
#define OUTW    506
#define RAWSTR  160                  // raw row stride bytes (40 words, ==8 mod 32)
#define WSTR    (27 * RAWSTR)        // 4320 per warp
#define SMEMTOT (WPC * WSTR)         // 17280 per CTA -> 8 CTAs/SM (smem-wise)

__device__ __forceinline__ uint32_t smem_u32(const void* p) {
    uint32_t a;
    asm("{ .reg .u64 t; cvta.to.shared.u64 t, %1; cvt.u32.u64 %0, t; }" : "=r"(a) : "l"(p));
    return a;
}
__device__ __forceinline__ uint32_t pack_bf16x2(float lo, float hi) {
    uint32_t r;  // d = { cvt(hi)=upper16 | cvt(lo)=lower16 }
    asm("cvt.rn.bf16x2.f32 %0, %1, %2;" : "=r"(r) : "f"(hi), "f"(lo));
    return r;
}
__device__ __forceinline__ float bf_lo(uint32_t p) { return __uint_as_float(p << 16); }
__device__ __forceinline__ float bf_hi(uint32_t p) { return __uint_as_float(p & 0xFFFF0000u); }

__device__ __forceinline__ void cpasync16(uint32_t dst, const float4* src, bool pred) {
    asm volatile("{\n\t.reg .pred p;\n\tsetp.ne.u32 p, %2, 0;\n\t"
                 "@p cp.async.cg.shared.global [%0], [%1], 16;\n\t}"
                 :: "r"(dst), "l"(src), "r"((uint32_t)pred));
}
#define CP_COMMIT() asm volatile("cp.async.commit_group;" ::: "memory")
#define CP_WAIT0()  asm volatile("cp.async.wait_group 0;"  ::: "memory")

// load 2 fp32 from smem, split into bf16x2 hi and lo regs
__device__ __forceinline__ void ld2_split(uint32_t addr, uint32_t& h, uint32_t& l) {
    float f0, f1;
    asm volatile("ld.shared.v2.f32 {%0, %1}, [%2];" : "=f"(f0), "=f"(f1) : "r"(addr));
    h = pack_bf16x2(f0, f1);
    l = pack_bf16x2(f0 - bf_lo(h), f1 - bf_hi(h));
}

__device__ __forceinline__ void mma16816(float* d, const uint32_t* a,
                                         uint32_t b0, uint32_t b1) {
    asm volatile("mma.sync.aligned.m16n8k16.row.col.f32.bf16.bf16.f32 "
                 "{%0,%1,%2,%3}, {%4,%5,%6,%7}, {%8,%9}, {%0,%1,%2,%3};"
                 : "+f"(d[0]), "+f"(d[1]), "+f"(d[2]), "+f"(d[3])
                 : "r"(a[0]), "r"(a[1]), "r"(a[2]), "r"(a[3]), "r"(b0), "r"(b1));
}
__device__ __forceinline__ void do_pair(float* c00, float* c01, float* c02, float* c03,
                                        float* c12, float* c13,
                                        const uint32_t* S0, const uint32_t* S1,
                                        const uint32_t* T0, const uint32_t* T1) {
    mma16816(c00, S0, T0[0], T0[2]);
    mma16816(c01, S0, T0[1], T0[3]);
    mma16816(c02, S0, T1[0], T1[2]);
    mma16816(c03, S0, T1[1], T1[3]);
    mma16816(c12, S1, T1[0], T1[2]);
    mma16816(c13, S1, T1[1], T1[3]);
}

extern __shared__ char smem[];

__global__ void __launch_bounds__(THREADS, 8)
dot_interact_mma(const float4* __restrict__ dense4,
                 const float4* __restrict__ sparse4,
                 float* __restrict__ out, int B)
{
    const int warp = threadIdx.x >> 5;
    const int lane = threadIdx.x & 31;
    const int b    = blockIdx.x * WPC + warp;
    if (b >= B) return;

    const uint32_t rawBase = smem_u32(smem) + warp * WSTR;

    // ---- staging plan (cp.async): it = 0..6, row r0 + 4*it, c4 = lane&7 ----
    const int r0 = lane >> 3;                      // 0..3
    const int c4 = lane & 7;
    const bool dlane   = (r0 == 0);                // it==0 reads dense
    const bool tail_ok = (lane < 24);              // it==6 rows 24..26 only
    const float4* dptr = dense4 + (long long)b * 32 + c4;
    const float4* sptr = sparse4 + ((long long)b * 26 + (r0 - 1)) * 32 + c4;
    const uint32_t wOff0 = (uint32_t)(r0 * RAWSTR + c4 * 16);

    // ---- fragment plan: fr = lane>>2 (0..7), fc = lane&3; row 24+fr clamped ----
    const int fr = lane >> 2;
    const int fc = lane & 3;
    const uint32_t A0 = rawBase + (uint32_t)(fr * RAWSTR + fc * 8);   // rows fr/fr+8/fr+16 via imm
    const int r24 = (fr + 24 > 26) ? 26 : (fr + 24);                  // clamp
    const uint32_t A3 = rawBase + (uint32_t)(r24 * RAWSTR + fc * 8);

    float c00[4] = {0,0,0,0}, c01[4] = {0,0,0,0}, c02[4] = {0,0,0,0};
    float c03[4] = {0,0,0,0}, c12[4] = {0,0,0,0}, c13[4] = {0,0,0,0};

    float2* out2 = reinterpret_cast<float2*>(out) + (long long)b * (OUTW / 2);

    // ---- prologue: async-load chunk 0 ----
    #pragma unroll
    for (int it = 0; it < 7; it++) {
        bool pred = (it < 6) | tail_ok;
        const float4* src = (it == 0 && dlane) ? dptr : (sptr + it * 128);
        cpasync16(rawBase + wOff0 + it * (4 * RAWSTR), src, pred);
    }
    CP_COMMIT();

    #pragma unroll
    for (int kc = 0; kc < 4; kc++) {
        CP_WAIT0();
        __syncwarp();    // all lanes' chunk-kc data visible (cross-lane reads)

        // ---- dense passthrough: row 0 = dense[b][32kc..] (lanes 0..15) ----
        if (lane < 16) {
            float2 dv;
            asm volatile("ld.shared.v2.f32 {%0, %1}, [%2];"
                         : "=f"(dv.x), "=f"(dv.y) : "r"(rawBase + lane * 8));
            out2[kc * 16 + lane] = dv;
        }

        // ---- k-step 0: build frags, MMA x3 ----
        {
            uint32_t S0h[4], S0l[4], S1h[4], S1l[4];
            ld2_split(A0,                      S0h[0], S0l[0]);
            ld2_split(A0 + 8 * RAWSTR,         S0h[1], S0l[1]);
            ld2_split(A0 + 32,                 S0h[2], S0l[2]);
            ld2_split(A0 + 8 * RAWSTR + 32,    S0h[3], S0l[3]);
            ld2_split(A0 + 16 * RAWSTR,        S1h[0], S1l[0]);
            ld2_split(A3,                      S1h[1], S1l[1]);
            ld2_split(A0 + 16 * RAWSTR + 32,   S1h[2], S1l[2]);
            ld2_split(A3 + 32,                 S1h[3], S1l[3]);
            do_pair(c00, c01, c02, c03, c12, c13, S0h, S1h, S0h, S1h);
            do_pair(c00, c01, c02, c03, c12, c13, S0h, S1h, S0l, S1l);
            do_pair(c00, c01, c02, c03, c12, c13, S0l, S1l, S0h, S1h);
        }
        // ---- k-step 1: build frags, then refill, then MMA x3 ----
        {
            uint32_t S0h[4], S0l[4], S1h[4], S1l[4];
            ld2_split(A0 + 64,                 S0h[0], S0l[0]);
            ld2_split(A0 + 8 * RAWSTR + 64,    S0h[1], S0l[1]);
            ld2_split(A0 + 96,                 S0h[2], S0l[2]);
            ld2_split(A0 + 8 * RAWSTR + 96,    S0h[3], S0l[3]);
            ld2_split(A0 + 16 * RAWSTR + 64,   S1h[0], S1l[0]);
            ld2_split(A3 + 64,                 S1h[1], S1l[1]);
            ld2_split(A0 + 16 * RAWSTR + 96,   S1h[2], S1l[2]);
            ld2_split(A3 + 96,                 S1h[3], S1l[3]);

            if (kc < 3) {     // all raw reads of chunk kc done -> refill
                __syncwarp();
                #pragma unroll
                for (int it = 0; it < 7; it++) {
                    bool pred = (it < 6) | tail_ok;
                    const float4* src = (it == 0 && dlane) ? (dptr + (kc + 1) * 8)
                                                           : (sptr + (kc + 1) * 8 + it * 128);
                    cpasync16(rawBase + wOff0 + it * (4 * RAWSTR), src, pred);
                }
                CP_COMMIT();
            }
            do_pair(c00, c01, c02, c03, c12, c13, S0h, S1h, S0h, S1h);
            do_pair(c00, c01, c02, c03, c12, c13, S0h, S1h, S0l, S1l);
            do_pair(c00, c01, c02, c03, c12, c13, S0l, S1l, S0h, S1h);
        }
    }

    // ---- epilogue: fragments -> FLAT triu stage (378 floats, reuse raw) ----
    float* stage = reinterpret_cast<float*>(smem + warp * WSTR);
    {
        const int er = lane >> 2;                 // 0..7
        const int ec = 2 * (lane & 3);            // 0,2,4,6
        float* t[6] = {c00, c01, c02, c03, c12, c13};
        const int mi[6] = {0, 0, 0, 0, 16, 16};
        const int nj[6] = {0, 8, 16, 24, 16, 24};
        #pragma unroll
        for (int q = 0; q < 6; q++) {
            int i0 = mi[q] + er, j0 = nj[q] + ec;
            #pragma unroll
            for (int e = 0; e < 4; e++) {
                int i = i0 + (e >> 1) * 8;
                int j = j0 + (e & 1);
                if (j >= i && j <= 26) {
                    stage[26 * i - ((i * (i - 1)) >> 1) + j] = t[q][e];
                }
            }
        }
    }
    __syncwarp();

    {   // coalesced triu write: 189 float2 per sample
        float2* st2  = reinterpret_cast<float2*>(stage);
        float2* orow = reinterpret_cast<float2*>(out + (long long)b * OUTW + 128);
        #pragma unroll
        for (int t = 0; t < 6; t++) {
            int idx = t * 32 + lane;
            if (idx < 189) orow[idx] = st2[idx];
        }
    }
}

extern "C" void kernel_launch(void* const* d_in, const int* in_sizes, int n_in,
                              void* d_out, int out_size)
{
    const float4* dense4  = (const float4*)d_in[0];
    const float4* sparse4 = (const float4*)d_in[1];
    float*        out     = (float*)d_out;

    int B = in_sizes[0] / 128;
    int grid = (B + WPC - 1) / WPC;

    cudaFuncSetAttribute(dot_interact_mma,
                         cudaFuncAttributeMaxDynamicSharedMemorySize, SMEMTOT);
    dot_interact_mma<<<grid, THREADS, SMEMTOT>>>(dense4, sparse4, out, B);
    (void)n_in; (void)out_size;
}

// round 17
// speedup vs baseline: 1.0342x; 1.0342x over previous
#include <cuda_runtime.h>
#include <cuda_bf16.h>
#include <cstdint>

// DotInteract: out[b] = concat(dense[b] (128), triu(C C^T) (378)),
// C = [dense[b]; sparse[b,0..25]] (27x128 fp32). B = 32768, OUTW = 506.
//
// One warp per sample; Gram via mma.sync.m16n8k16 bf16, hi+lo split, 3 passes
// (err ~3e-6). Fragments built directly from a cp.async'd raw fp32 buffer via
// LDS.64 + in-register split; A-frag regs double as B-frags (C.C^T symmetry).
// R17 = R14 (best measured: 64-float k-block buffer, 2 fills, 7 CTAs/SM,
// 72 regs) + .cs streaming hints on ALL output stores so the 66 MB write
// stream doesn't evict the read stream from L2.

#define THREADS 128
#define WPC     4                    // warps = samples per CTA
#define OUTW    506
#define RAWSTR  288                  // raw row stride bytes (72 words, ==8 mod 32 banks)
#define WSTR    (27 * RAWSTR)        // 7776 per warp
#define SMEMTOT (WPC * WSTR)         // 31104 per CTA -> 7 CTAs/SM

__device__ __forceinline__ uint32_t smem_u32(const void* p) {
    uint32_t a;
    asm("{ .reg .u64 t; cvta.to.shared.u64 t, %1; cvt.u32.u64 %0, t; }" : "=r"(a) : "l"(p));
    return a;
}
__device__ __forceinline__ uint32_t pack_bf16x2(float lo, float hi) {
    uint32_t r;  // d = { cvt(hi)=upper16 | cvt(lo)=lower16 }
    asm("cvt.rn.bf16x2.f32 %0, %1, %2;" : "=r"(r) : "f"(hi), "f"(lo));
    return r;
}
__device__ __forceinline__ float bf_lo(uint32_t p) { return __uint_as_float(p << 16); }
__device__ __forceinline__ float bf_hi(uint32_t p) { return __uint_as_float(p & 0xFFFF0000u); }

__device__ __forceinline__ void cpasync16(uint32_t dst, const float4* src, bool pred) {
    asm volatile("{\n\t.reg .pred p;\n\tsetp.ne.u32 p, %2, 0;\n\t"
                 "@p cp.async.cg.shared.global [%0], [%1], 16;\n\t}"
                 :: "r"(dst), "l"(src), "r"((uint32_t)pred));
}
#define CP_COMMIT() asm volatile("cp.async.commit_group;" ::: "memory")
#define CP_WAIT0()  asm volatile("cp.async.wait_group 0;"  ::: "memory")

// streaming (evict-first) float2 store
__device__ __forceinline__ void stg_cs_f2(float2* dst, float x, float y) {
    asm volatile("st.global.cs.v2.f32 [%0], {%1, %2};" :: "l"(dst), "f"(x), "f"(y) : "memory");
}

// load 2 fp32 from smem, split into bf16x2 hi and lo regs
__device__ __forceinline__ void ld2_split(uint32_t addr, uint32_t& h, uint32_t& l) {
    float f0, f1;
    asm volatile("ld.shared.v2.f32 {%0, %1}, [%2];" : "=f"(f0), "=f"(f1) : "r"(addr));
    h = pack_bf16x2(f0, f1);
    l = pack_bf16x2(f0 - bf_lo(h), f1 - bf_hi(h));
}

__device__ __forceinline__ void mma16816(float* d, const uint32_t* a,
                                         uint32_t b0, uint32_t b1) {
    asm volatile("mma.sync.aligned.m16n8k16.row.col.f32.bf16.bf16.f32 "
                 "{%0,%1,%2,%3}, {%4,%5,%6,%7}, {%8,%9}, {%0,%1,%2,%3};"
                 : "+f"(d[0]), "+f"(d[1]), "+f"(d[2]), "+f"(d[3])
                 : "r"(a[0]), "r"(a[1]), "r"(a[2]), "r"(a[3]), "r"(b0), "r"(b1));
}
__device__ __forceinline__ void do_pair(float* c00, float* c01, float* c02, float* c03,
                                        float* c12, float* c13,
                                        const uint32_t* S0, const uint32_t* S1,
                                        const uint32_t* T0, const uint32_t* T1) {
    mma16816(c00, S0, T0[0], T0[2]);
    mma16816(c01, S0, T0[1], T0[3]);
    mma16816(c02, S0, T1[0], T1[2]);
    mma16816(c03, S0, T1[1], T1[3]);
    mma16816(c12, S1, T1[0], T1[2]);
    mma16816(c13, S1, T1[1], T1[3]);
}

extern __shared__ char smem[];

__global__ void __launch_bounds__(THREADS, 7)
dot_interact_mma(const float4* __restrict__ dense4,
                 const float4* __restrict__ sparse4,
                 float* __restrict__ out, int B)
{
    const int warp = threadIdx.x >> 5;
    const int lane = threadIdx.x & 31;
    const int b    = blockIdx.x * WPC + warp;
    if (b >= B) return;

    const uint32_t rawBase = smem_u32(smem) + warp * WSTR;

    // ---- staging plan: it = 0..13, row r = 2*it + r0l, col16 = lane&15 ----
    const int r0l = lane >> 4;                     // 0 or 1
    const int c16 = lane & 15;
    const bool dlane = (r0l == 0);                 // it==0, r0l==0 reads dense
    const float4* dptr = dense4 + (long long)b * 32 + c16;
    const float4* sptr = sparse4 + ((long long)b * 26 + (r0l - 1)) * 32 + c16;
    const uint32_t wOff0 = (uint32_t)(r0l * RAWSTR + c16 * 16);

    // ---- fragment plan: fr = lane>>2 (0..7), fc = lane&3; rows clamped ----
    const int fr = lane >> 2;
    const int fc = lane & 3;
    const uint32_t A0 = rawBase + (uint32_t)(fr * RAWSTR + fc * 8);
    const uint32_t A1 = A0 + 8 * RAWSTR;
    const uint32_t A2 = A0 + 16 * RAWSTR;                        // rows 16..23
    const int r24 = (fr + 24 > 26) ? 26 : (fr + 24);             // clamp
    const uint32_t A3 = rawBase + (uint32_t)(r24 * RAWSTR + fc * 8);

    float c00[4] = {0,0,0,0}, c01[4] = {0,0,0,0}, c02[4] = {0,0,0,0};
    float c03[4] = {0,0,0,0}, c12[4] = {0,0,0,0}, c13[4] = {0,0,0,0};

    float2* out2 = reinterpret_cast<float2*>(out) + (long long)b * (OUTW / 2);

    // ---- prologue: async-load k-block 0 (cols 0..63) ----
    #pragma unroll
    for (int it = 0; it < 14; it++) {
        bool pred = (it < 13) | dlane;             // skip row 27 (it==13, r0l==1)
        const float4* src = (it == 0 && dlane) ? dptr : (sptr + it * 64);
        cpasync16(rawBase + wOff0 + it * (2 * RAWSTR), src, pred);
    }
    CP_COMMIT();

    #pragma unroll
    for (int kb = 0; kb < 2; kb++) {
        CP_WAIT0();
        __syncwarp();    // all lanes' fill visible (cross-lane reads)

        // ---- dense passthrough: row 0 = dense[b][64kb..64kb+63] ----
        {
            float2 dv;
            asm volatile("ld.shared.v2.f32 {%0, %1}, [%2];"
                         : "=f"(dv.x), "=f"(dv.y) : "r"(rawBase + lane * 8));
            stg_cs_f2(out2 + kb * 32 + lane, dv.x, dv.y);
        }

        // ---- 4 k-steps: build frags (8 LDS.64 + split) then MMA ----
        #pragma unroll
        for (int ks = 0; ks < 4; ks++) {
            uint32_t o = ks * 64;
            uint32_t S0h[4], S0l[4], S1h[4], S1l[4];
            ld2_split(A0 + o,      S0h[0], S0l[0]);
            ld2_split(A1 + o,      S0h[1], S0l[1]);
            ld2_split(A0 + o + 32, S0h[2], S0l[2]);
            ld2_split(A1 + o + 32, S0h[3], S0l[3]);
            ld2_split(A2 + o,      S1h[0], S1l[0]);
            ld2_split(A3 + o,      S1h[1], S1l[1]);
            ld2_split(A2 + o + 32, S1h[2], S1l[2]);
            ld2_split(A3 + o + 32, S1h[3], S1l[3]);

            if (ks == 3 && kb == 0) {
                // all reads of fill 0 done -> refill with k-block 1
                __syncwarp();
                #pragma unroll
                for (int it = 0; it < 14; it++) {
                    bool pred = (it < 13) | dlane;
                    const float4* src = (it == 0 && dlane) ? (dptr + 16)
                                                           : (sptr + it * 64 + 16);
                    cpasync16(rawBase + wOff0 + it * (2 * RAWSTR), src, pred);
                }
                CP_COMMIT();
            }

            do_pair(c00, c01, c02, c03, c12, c13, S0h, S1h, S0h, S1h);  // hi.hi
            do_pair(c00, c01, c02, c03, c12, c13, S0h, S1h, S0l, S1l);  // hi.lo
            do_pair(c00, c01, c02, c03, c12, c13, S0l, S1l, S0h, S1h);  // lo.hi
        }
    }

    // ---- epilogue: fragments -> FLAT triu stage (378 floats, reuse raw) ----
    float* stage = reinterpret_cast<float*>(smem + warp * WSTR);
    {
        const int er = lane >> 2;                 // 0..7
        const int ec = 2 * (lane & 3);            // 0,2,4,6
        float* t[6] = {c00, c01, c02, c03, c12, c13};
        const int mi[6] = {0, 0, 0, 0, 16, 16};
        const int nj[6] = {0, 8, 16, 24, 16, 24};
        #pragma unroll
        for (int q = 0; q < 6; q++) {
            int i0 = mi[q] + er, j0 = nj[q] + ec;
            #pragma unroll
            for (int e = 0; e < 4; e++) {
                int i = i0 + (e >> 1) * 8;
                int j = j0 + (e & 1);
                if (j >= i && j <= 26) {
                    stage[26 * i - ((i * (i - 1)) >> 1) + j] = t[q][e];
                }
            }
        }
    }
    __syncwarp();

    {   // coalesced streaming triu write: 189 float2 per sample
        float2* st2  = reinterpret_cast<float2*>(stage);
        float2* orow = reinterpret_cast<float2*>(out + (long long)b * OUTW + 128);
        #pragma unroll
        for (int t = 0; t < 6; t++) {
            int idx = t * 32 + lane;
            if (idx < 189) {
                float2 v = st2[idx];
                stg_cs_f2(orow + idx, v.x, v.y);
            }
        }
    }
}

extern "C" void kernel_launch(void* const* d_in, const int* in_sizes, int n_in,
                              void* d_out, int out_size)
{
    const float4* dense4  = (const float4*)d_in[0];
    const float4* sparse4 = (const float4*)d_in[1];
    float*        out     = (float*)d_out;

    int B = in_sizes[0] / 128;
    int grid = (B + WPC - 1) / WPC;

    cudaFuncSetAttribute(dot_interact_mma,
                         cudaFuncAttributeMaxDynamicSharedMemorySize, SMEMTOT);
    dot_interact_mma<<<grid, THREADS, SMEMTOT>>>(dense4, sparse4, out, B);
    (void)n_in; (void)out_size;
}